// round 8
// baseline (speedup 1.0000x reference)
#include <cuda_runtime.h>

// Problem constants
#define F_DENSE  13
#define F_SPARSE 26
#define NF       39          // F_DENSE + F_SPARSE
#define E_DIM    16
#define VOC      100000
#define H1       512
#define H2       256
#define D_IN     624         // (13+26)*16

#define THREADS   256
#define TILE      16         // samples per tile (2 per warp * 8 warps)
#define GRID_MAIN 512        // each block does exactly 2 tiles (1024 tiles)

// Scratch (device globals; no allocation allowed)
__device__ float g_w2eff[H1];
__device__ float g_w1eff[D_IN];
__device__ float g_CONST;

// ---------------------------------------------------------------------------
// Prep A: w2eff[k] = sum_j Lw2[k,j] * g2[j]   (one warp per k)
// ---------------------------------------------------------------------------
__global__ void prep_w2eff(const float* __restrict__ Lw2,
                           const float* __restrict__ g2) {
    int w    = (blockIdx.x * blockDim.x + threadIdx.x) >> 5;
    int lane = threadIdx.x & 31;
    if (w >= H1) return;
    float acc = 0.f;
#pragma unroll
    for (int i = 0; i < H2 / 32; i++) {
        int j = lane + i * 32;
        acc = fmaf(__ldg(Lw2 + w * H2 + j), __ldg(g2 + j), acc);
    }
#pragma unroll
    for (int o = 16; o; o >>= 1) acc += __shfl_xor_sync(0xffffffffu, acc, o);
    if (lane == 0) g_w2eff[w] = acc;
}

// ---------------------------------------------------------------------------
// Prep B (fused): blocks 0..77 compute w1eff (one warp per d, 624 warps);
// block 78 computes the scalar constant.
// ---------------------------------------------------------------------------
__global__ void prep_w1eff_const(const float* __restrict__ Lw1,
                                 const float* __restrict__ g1,
                                 const float* __restrict__ Lb1,
                                 const float* __restrict__ be1,
                                 const float* __restrict__ Lb2,
                                 const float* __restrict__ g2,
                                 const float* __restrict__ be2) {
    if (blockIdx.x < 78) {
        int w    = (blockIdx.x * blockDim.x + threadIdx.x) >> 5;  // 0..623
        int lane = threadIdx.x & 31;
        if (w >= D_IN) return;
        float acc = 0.f;
#pragma unroll
        for (int i = 0; i < H1 / 32; i++) {
            int k = lane + i * 32;
            acc = fmaf(__ldg(Lw1 + w * H1 + k), __ldg(g1 + k) * g_w2eff[k], acc);
        }
#pragma unroll
        for (int o = 16; o; o >>= 1) acc += __shfl_xor_sync(0xffffffffu, acc, o);
        if (lane == 0) g_w1eff[w] = acc;
    } else {
        // CONST = inv^2*sum_k g1*w2eff*Lb1 + inv*sum_k be1*w2eff
        //       + inv*sum_j g2*Lb2 + sum_j be2
        const float inv = rsqrtf(1.f + 1e-5f);
        int t = threadIdx.x;                 // 256 threads, 2 k's each
        float v = 0.f;
#pragma unroll
        for (int r = 0; r < 2; r++) {
            int k = t + r * 256;
            float w2e = g_w2eff[k];
            v += inv * inv * g1[k] * w2e * Lb1[k] + inv * be1[k] * w2e;
            if (k < H2) v += inv * g2[k] * Lb2[k] + be2[k];
        }
        __shared__ float sh[256];
        sh[t] = v;
        __syncthreads();
        for (int s = 128; s; s >>= 1) {
            if (t < s) sh[t] += sh[t + s];
            __syncthreads();
        }
        if (t == 0) g_CONST = sh[0];
    }
}

// ---------------------------------------------------------------------------
// Batched sparse chunk: CH slots, both tables (2*CH loads in flight).
// Pure broadcast-__ldg addressing (no smem chain in front of gathers).
// ---------------------------------------------------------------------------
template <int CH>
__device__ __forceinline__ void slots_chunk(
    int c0, const int* __restrict__ xi, const float* __restrict__ xv, int e,
    const float* __restrict__ emb1, const float* __restrict__ emb2,
    float& fm1, float& se, float& ss, float& hd)
{
    int   off[CH];
    float vv[CH];
#pragma unroll
    for (int j = 0; j < CH; j++) {
        int s  = c0 + j;
        int id = __ldg(xi + F_DENSE + s);
        vv[j]  = __ldg(xv + F_DENSE + s);
        off[j] = (s * VOC + id) * E_DIM + e;
    }
    float a1[CH], a2[CH];
#pragma unroll
    for (int j = 0; j < CH; j++) a2[j] = __ldg(emb2 + off[j]);
#pragma unroll
    for (int j = 0; j < CH; j++) a1[j] = __ldg(emb1 + off[j]);
#pragma unroll
    for (int j = 0; j < CH; j++) {
        int s = c0 + j;
        float v   = vv[j];
        float sev = a2[j] * v;
        fm1 = fmaf(a1[j], v, fm1);
        se += sev;
        ss  = fmaf(sev, sev, ss);
        hd  = fmaf(sev, __ldg(g_w1eff + (F_DENSE + s) * E_DIM + e), hd);
    }
}

// ---------------------------------------------------------------------------
// Main kernel: 16 lanes per sample (lane = e), 2 samples per warp.
// Persistent over tiles: grid=512, each block strides through 1024 tiles
// (exactly 2 each) -> single wave, no ragged tail.
// ---------------------------------------------------------------------------
__global__ __launch_bounds__(THREADS, 4) void deepfm_main(
    const int*   __restrict__ Xi,
    const float* __restrict__ Xv,
    const float* __restrict__ W1,
    const float* __restrict__ b1,
    const float* __restrict__ emb1,
    const float* __restrict__ W2,
    const float* __restrict__ b2,
    const float* __restrict__ emb2,
    const float* __restrict__ bias,
    float*       __restrict__ out,
    int n, int ntiles) {
    const float inv2 = 1.f / (1.f + 1e-5f);   // inv^2 = 1/(1+eps)

    int tid  = threadIdx.x;
    int lane = tid & 31;
    int e    = lane & 15;          // embedding column handled by this lane
    int sub  = lane >> 4;          // 0/1: sample within warp
    int warp = tid >> 5;
    unsigned smask = 0xFFFFu << (sub << 4);   // this sample's half-warp

    for (int tile = blockIdx.x; tile < ntiles; tile += gridDim.x) {
        int b = (tile << 4) + (warp << 1) + sub;
        if (b < n) {
            const int*   xi = Xi + b * NF;
            const float* xv = Xv + b * NF;

            float fm1 = 0.f;   // first-order sum (partial over this lane's e)
            float se  = 0.f;   // sum_emb[e]
            float ss  = 0.f;   // sumsq[e]
            float hd  = 0.f;   // h . w1eff (partial)

            // Sparse gathers: 6 chunks of 4 + 1 of 2 (8 loads in flight each)
            slots_chunk<4>( 0, xi, xv, e, emb1, emb2, fm1, se, ss, hd);
            slots_chunk<4>( 4, xi, xv, e, emb1, emb2, fm1, se, ss, hd);
            slots_chunk<4>( 8, xi, xv, e, emb1, emb2, fm1, se, ss, hd);
            slots_chunk<4>(12, xi, xv, e, emb1, emb2, fm1, se, ss, hd);
            slots_chunk<4>(16, xi, xv, e, emb1, emb2, fm1, se, ss, hd);
            slots_chunk<4>(20, xi, xv, e, emb1, emb2, fm1, se, ss, hd);
            slots_chunk<2>(24, xi, xv, e, emb1, emb2, fm1, se, ss, hd);

            // Dense features (params L1/L2-resident)
#pragma unroll
            for (int f = 0; f < F_DENSE; f++) {
                float x  = (float)__ldg(xi + f);
                float v  = __ldg(xv + f);
                int   o  = f * E_DIM + e;
                float sl = fmaf(x, __ldg(W2 + o), __ldg(b2 + o));   // sec_lin
                fm1 = fmaf(fmaf(x, __ldg(W1 + o), __ldg(b1 + o)), v, fm1);
                se += sl;
                ss  = fmaf(sl, sl, ss);
                hd  = fmaf(sl, __ldg(g_w1eff + o), hd);
            }

            // Per-lane combined partial; fm_second per-e is exact here
            float r = fm1 + 0.5f * (se * se - ss) + inv2 * hd;

            // Fold 16 lanes within this sample's half-warp
#pragma unroll
            for (int o = 1; o < 16; o <<= 1) r += __shfl_xor_sync(smask, r, o);

            if (e == 0) out[b] = r + g_CONST + __ldg(bias + b);
        }
    }
}

// ---------------------------------------------------------------------------
extern "C" void kernel_launch(void* const* d_in, const int* in_sizes, int n_in,
                              void* d_out, int out_size) {
    const int*   Xi   = (const int*)  d_in[0];
    const float* Xv   = (const float*)d_in[1];
    const float* W1   = (const float*)d_in[2];
    const float* b1   = (const float*)d_in[3];
    const float* emb1 = (const float*)d_in[4];
    const float* W2   = (const float*)d_in[5];
    const float* b2   = (const float*)d_in[6];
    const float* emb2 = (const float*)d_in[7];
    const float* Lw1  = (const float*)d_in[8];
    const float* Lb1  = (const float*)d_in[9];
    const float* g1   = (const float*)d_in[10];
    const float* be1  = (const float*)d_in[11];
    const float* Lw2  = (const float*)d_in[12];
    const float* Lb2  = (const float*)d_in[13];
    const float* g2   = (const float*)d_in[14];
    const float* be2  = (const float*)d_in[15];
    const float* bias = (const float*)d_in[16];
    float* out = (float*)d_out;

    // Prep: collapse the MLP into one 624-vector + scalar (2 launches)
    prep_w2eff<<<(H1 * 32 + 255) / 256, 256>>>(Lw2, g2);
    prep_w1eff_const<<<79, 256>>>(Lw1, g1, Lb1, be1, Lb2, g2, be2);

    int n      = out_size;
    int ntiles = (n + TILE - 1) / TILE;
    int grid   = ntiles < GRID_MAIN ? ntiles : GRID_MAIN;
    deepfm_main<<<grid, THREADS>>>(Xi, Xv, W1, b1, emb1, W2, b2, emb2,
                                   bias, out, n, ntiles);
}